// round 11
// baseline (speedup 1.0000x reference)
#include <cuda_runtime.h>
#include <cuda_fp16.h>
#include <cstdint>

#define NN     8192
#define F_IN   128
#define F_OUTD 64
#define L2E    1.4426950408889634f

#define ALPHA2_PK 0x32663266u   // half2(0.2, 0.2)
#define MESH2_PK  0xC5C5C5C5u   // half2(-5.7695, -5.7695) (~ -4*log2(e); uniform
                                // offset, cancels exactly in softmax)

// ---------------------------------------------------------------------------
// Device scratch (allocations forbidden -> __device__ globals)
// ---------------------------------------------------------------------------
__device__ float    g_wh[NN * F_OUTD];
__device__ __half   g_whT16[F_OUTD * NN];    // [f][i] fp16 transpose of wh
__device__ float    g_src[NN];
__device__ float    g_dst[NN];
__device__ uint32_t g_dst16u[NN / 2];        // half2(dst[2u], dst[2u+1]) * L2E
__device__ float    g_part[256 * 128 * 66];  // [cta][row][64 num, 1 Z, pad]

// ---------------------------------------------------------------------------
// Kernel 1: WH = H @ W (fp32) + fp16 transpose WH^T. 32 rows per block.
// ---------------------------------------------------------------------------
__global__ __launch_bounds__(256) void wh_kernel(const float* __restrict__ h,
                                                 const float* __restrict__ w) {
    __shared__ __align__(16) float sW[F_IN * F_OUTD];  // 32 KB
    __shared__ __align__(16) float sH[32 * F_IN];      // 16 KB (reused as sT)
    int t = threadIdx.x;
    int i0 = blockIdx.x * 32;

    {
        float4* dw = (float4*)sW;
        const float4* swg = (const float4*)w;
        #pragma unroll
        for (int k = 0; k < 8; k++) dw[t + k * 256] = swg[t + k * 256];
        float4* dh = (float4*)sH;
        const float4* shg = (const float4*)(h + (size_t)i0 * F_IN);
        #pragma unroll
        for (int k = 0; k < 4; k++) dh[t + k * 256] = shg[t + k * 256];
    }
    __syncthreads();

    int f = t & 63;
    int rg = t >> 6;
    float acc[8] = {0.f, 0.f, 0.f, 0.f, 0.f, 0.f, 0.f, 0.f};
    #pragma unroll 4
    for (int k = 0; k < F_IN; k += 4) {
        float w0 = sW[(k + 0) * F_OUTD + f];
        float w1 = sW[(k + 1) * F_OUTD + f];
        float w2 = sW[(k + 2) * F_OUTD + f];
        float w3 = sW[(k + 3) * F_OUTD + f];
        #pragma unroll
        for (int m = 0; m < 8; m++) {
            float4 h4 = *(const float4*)&sH[(rg * 8 + m) * F_IN + k];
            acc[m] = fmaf(h4.x, w0, acc[m]);
            acc[m] = fmaf(h4.y, w1, acc[m]);
            acc[m] = fmaf(h4.z, w2, acc[m]);
            acc[m] = fmaf(h4.w, w3, acc[m]);
        }
    }
    #pragma unroll
    for (int m = 0; m < 8; m++)
        g_wh[(size_t)(i0 + rg * 8 + m) * F_OUTD + f] = acc[m];

    __syncthreads();
    __half* sT = (__half*)sH;   // [64 f][32 r]
    #pragma unroll
    for (int m = 0; m < 8; m++)
        sT[f * 32 + rg * 8 + m] = __float2half_rn(acc[m]);
    __syncthreads();
    {
        int f2 = t >> 2, seg = t & 3;
        uint4 v = *(const uint4*)(sT + f2 * 32 + seg * 8);
        *(uint4*)(g_whT16 + (size_t)f2 * NN + i0 + seg * 8) = v;
    }
}

// ---------------------------------------------------------------------------
// Kernel 2: src / dst vectors
// ---------------------------------------------------------------------------
__global__ __launch_bounds__(256) void srcdst_kernel(const float* __restrict__ edge,
                                                     const float* __restrict__ att,
                                                     const float* __restrict__ w_edge) {
    int warp = threadIdx.x >> 5;
    int lane = threadIdx.x & 31;
    int i = blockIdx.x * 8 + warp;
    const float* whr = g_wh + (size_t)i * F_OUTD;

    float wl = whr[lane], wh2 = whr[lane + 32];
    float s = wl * att[lane]      + wh2 * att[lane + 32];
    float d = wl * att[64 + lane] + wh2 * att[96 + lane];
    float c = w_edge[lane] * att[128 + lane] + w_edge[lane + 32] * att[160 + lane];
    #pragma unroll
    for (int o = 16; o; o >>= 1) {
        s += __shfl_xor_sync(0xffffffffu, s, o);
        d += __shfl_xor_sync(0xffffffffu, d, o);
        c += __shfl_xor_sync(0xffffffffu, c, o);
    }
    if (lane == 0) {
        g_src[i] = s + edge[i] * c;
        g_dst[i] = d;
    }
}

// pack dst*L2E into half2 (even col in .lo)
__global__ __launch_bounds__(256) void packdst_kernel() {
    int u = blockIdx.x * 256 + threadIdx.x;   // 0..4095
    float2 d = *(const float2*)(g_dst + 2 * u);
    __half2 p = __floats2half2_rn(d.x * L2E, d.y * L2E);
    g_dst16u[u] = *(const uint32_t*)&p;
}

// ---------------------------------------------------------------------------
// mma.sync / ldmatrix helpers
// ---------------------------------------------------------------------------
__device__ __forceinline__ uint32_t smem_u32(const void* p) {
    uint32_t a;
    asm("{ .reg .u64 t; cvta.to.shared.u64 t, %1; cvt.u32.u64 %0, t; }"
        : "=r"(a) : "l"(p));
    return a;
}
__device__ __forceinline__ void mma16816(float* c, uint32_t a0, uint32_t a1,
                                         uint32_t a2, uint32_t a3,
                                         uint32_t b0, uint32_t b1) {
    asm volatile(
        "mma.sync.aligned.m16n8k16.row.col.f32.f16.f16.f32 "
        "{%0,%1,%2,%3}, {%4,%5,%6,%7}, {%8,%9}, {%0,%1,%2,%3};"
        : "+f"(c[0]), "+f"(c[1]), "+f"(c[2]), "+f"(c[3])
        : "r"(a0), "r"(a1), "r"(a2), "r"(a3), "r"(b0), "r"(b1));
}
__device__ __forceinline__ void ldsm_x4(uint32_t* r, uint32_t addr) {
    asm volatile("ldmatrix.sync.aligned.m8n8.x4.shared.b16 {%0,%1,%2,%3}, [%4];"
                 : "=r"(r[0]), "=r"(r[1]), "=r"(r[2]), "=r"(r[3]) : "r"(addr));
}
// streaming adjacency load, 16B (4 ints covering one lane's full k-step need)
__device__ __forceinline__ int4 ldcs4(const int* p) {
    int4 v;
    asm volatile("ld.global.cs.v4.s32 {%0, %1, %2, %3}, [%4];"
                 : "=r"(v.x), "=r"(v.y), "=r"(v.z), "=r"(v.w) : "l"(p));
    return v;
}
// packed fp16 attention pair: src2/d2 already *L2E; mask by multiply.
// w = 2^( leaky(L2E*(src+dst)) - 4*L2E ) * mask
__device__ __forceinline__ uint32_t wpair16(uint32_t src2, uint32_t d2,
                                            int ax, int ay) {
    uint32_t e, m, l, g, w;
    asm("add.f16x2 %0, %1, %2;"    : "=r"(e) : "r"(src2), "r"(d2));
    asm("mul.f16x2 %0, %1, %2;"    : "=r"(m) : "r"(e), "r"(ALPHA2_PK));
    asm("max.f16x2 %0, %1, %2;"    : "=r"(l) : "r"(e), "r"(m));
    asm("add.f16x2 %0, %1, %2;"    : "=r"(g) : "r"(l), "r"(MESH2_PK));
    asm("ex2.approx.f16x2 %0, %0;" : "+r"(g));
    uint32_t msk = (uint32_t)ax * 0x3C00u + (uint32_t)ay * 0x3C000000u;
    asm("mul.f16x2 %0, %1, %2;"    : "=r"(w) : "r"(g), "r"(msk));
    return w;
}

// ---------------------------------------------------------------------------
// Kernel 3: HMMA masked-softmax aggregation.
// Grid 256 = 64 row-blocks x 4 j-quarters; CTA = 128 threads / 4 warps,
// 2 CTAs/SM. Each warp owns M=32 rows {r, r+8, r+16, r+24}: B fragments
// (identical across warps) now feed 2x the MMA work, halving ldmatrix L1
// wavefronts per unit work (round-10 limiter). Fully-unrolled k-steps keep
// all ring indices literal; adj ring depth 4, dst ring depth 2.
// j-permutation per 16-col k-step group (adj = one int4/lane/row-group):
//   MMA cols (2*l4, 2*l4+1) <- j = 16ks + 4*l4 + {0,1}
//   MMA cols (2*l4+8,+9)    <- j = 16ks + 4*l4 + {2,3}
// Softmax is j-order invariant; Z (ones-B) unaffected.
// ---------------------------------------------------------------------------
__global__ void __launch_bounds__(128, 2) attn_kernel(const int* __restrict__ adj) {
    __shared__ __align__(1024) __half sB[2][64 * 128];   // 2 x 16 KB

    int t = threadIdx.x, lane = t & 31, w = t >> 5;
    int bx = blockIdx.x;
    int i0 = (bx >> 2) * 128, j0 = (bx & 3) * 2048;

    int l4 = lane & 3;
    int lr = lane >> 2;
    int row0 = w * 32 + lr;    // warp rows: row0, +8, +16, +24

    float acc[2][8][4];        // [m-tile][n-tile][frag]
    float zc[2][4];
    #pragma unroll
    for (int mt = 0; mt < 2; mt++) {
        #pragma unroll
        for (int p = 0; p < 8; p++)
            #pragma unroll
            for (int q = 0; q < 4; q++) acc[mt][p][q] = 0.f;
        #pragma unroll
        for (int q = 0; q < 4; q++) zc[mt][q] = 0.f;
    }

    // src * L2E, replicated half2, one per row-group
    uint32_t srcL[4];
    #pragma unroll
    for (int rg = 0; rg < 4; rg++) {
        __half2 sh = __float2half2_rn(g_src[i0 + row0 + 8 * rg] * L2E);
        srcL[rg] = *(const uint32_t*)&sh;
    }

    // adjacency bases: one int4 per k-step per row-group
    const int* ap0 = adj + (size_t)(i0 + row0) * NN + j0 + l4 * 4;
    const int* ap1 = ap0 + (size_t)8 * NN;
    const int* ap2 = ap0 + (size_t)16 * NN;
    const int* ap3 = ap0 + (size_t)24 * NN;
    // dst base: half2 units
    const uint32_t* dpp = g_dst16u + (j0 >> 1) + l4 * 2;

    // B-copy indices: 128 threads stage 16 KB -> 8 uint4 chunks each
    int fB = t >> 1, qb = (t & 1) * 8;
    const uint4* bsrc_base = (const uint4*)(g_whT16 + (size_t)fB * NN + j0);
    // ldmatrix per-lane geometry
    int fo  = (lane & 7) + ((lane & 16) >> 1);
    int cb  = (lane >> 3) & 1;
    int sw7 = lane & 7;
    uint32_t sb_base = smem_u32(sB);

    // B staging with half2-unit deinterleave per 32B group (4 groups/thread)
    #define STAGE_B(dstbuf, srcptr)                                             \
        do {                                                                    \
            char* db = (char*)(dstbuf) + (size_t)fB * 256;                      \
            _Pragma("unroll")                                                   \
            for (int gg = 0; gg < 4; gg++) {                                    \
                uint4 v0 = (srcptr)[qb + 2 * gg], v1 = (srcptr)[qb + 2 * gg + 1];\
                uint4 oe = make_uint4(v0.x, v0.z, v1.x, v1.z);                  \
                uint4 oo = make_uint4(v0.y, v0.w, v1.y, v1.w);                  \
                *(uint4*)(db + (((qb + 2 * gg + 0) ^ (fB & 7)) << 4)) = oe;     \
                *(uint4*)(db + (((qb + 2 * gg + 1) ^ (fB & 7)) << 4)) = oo;     \
            }                                                                   \
        } while (0)

    // prologue: fill B buffer 0
    STAGE_B(sB[0], bsrc_base);

    // prologue rings: adj steps 0..3 per row-group; dst steps 0..1
    int4 rA0[4], rA1[4], rA2[4], rA3[4];
    uint2 rD[2];
    #pragma unroll
    for (int st = 0; st < 4; st++) {
        rA0[st] = ldcs4(ap0 + st * 16);
        rA1[st] = ldcs4(ap1 + st * 16);
        rA2[st] = ldcs4(ap2 + st * 16);
        rA3[st] = ldcs4(ap3 + st * 16);
    }
    #pragma unroll
    for (int st = 0; st < 2; st++)
        rD[st] = *(const uint2*)(dpp + st * 8);

    const uint32_t ONES = 0x3C003C00u;  // fp16 {1,1}

    for (int lt = 0; lt < 16; lt++) {
        int s = lt & 1;
        __syncthreads();
        if (lt < 15) {   // prefetch next B tile into the other buffer
            const uint4* bs = (const uint4*)((const __half*)bsrc_base + (lt + 1) * 128);
            STAGE_B(sB[s ^ 1], bs);
        }

        uint32_t lmbase = sb_base + (uint32_t)s * 16384u + (uint32_t)fo * 256u;
        int gbase = lt * 8;

        #pragma unroll
        for (int ks = 0; ks < 8; ks++) {          // ks literal (unrolled)
            const int sa = ks & 3, sd = ks & 1;   // compile-time ring slots
            int4 a0 = rA0[sa], a1 = rA1[sa], a2 = rA2[sa], a3 = rA3[sa];
            uint2 dd = rD[sd];

            // refill slot sa with step g+4, slot sd with step g+2
            if (lt < 15 || ks < 4) {
                rA0[sa] = ldcs4(ap0 + (gbase + ks + 4) * 16);
                rA1[sa] = ldcs4(ap1 + (gbase + ks + 4) * 16);
                rA2[sa] = ldcs4(ap2 + (gbase + ks + 4) * 16);
                rA3[sa] = ldcs4(ap3 + (gbase + ks + 4) * 16);
            }
            if (lt < 15 || ks < 6)
                rD[sd] = *(const uint2*)(dpp + (gbase + ks + 2) * 8);

            // A fragments: m-tile 0 = rows (r, r+8), m-tile 1 = rows (+16, +24)
            uint32_t fa0 = wpair16(srcL[0], dd.x, a0.x, a0.y);   // r,    k-lo
            uint32_t fa1 = wpair16(srcL[1], dd.x, a1.x, a1.y);   // r+8,  k-lo
            uint32_t fa2 = wpair16(srcL[0], dd.y, a0.z, a0.w);   // r,    k-hi
            uint32_t fa3 = wpair16(srcL[1], dd.y, a1.z, a1.w);   // r+8,  k-hi
            uint32_t fb0 = wpair16(srcL[2], dd.x, a2.x, a2.y);   // r+16, k-lo
            uint32_t fb1 = wpair16(srcL[3], dd.x, a3.x, a3.y);   // r+24, k-lo
            uint32_t fb2 = wpair16(srcL[2], dd.y, a2.z, a2.w);   // r+16, k-hi
            uint32_t fb3 = wpair16(srcL[3], dd.y, a3.z, a3.w);   // r+24, k-hi

            uint32_t chx = (uint32_t)(((2 * ks + cb) ^ sw7) << 4);
            uint32_t b[16];
            #pragma unroll
            for (int pp = 0; pp < 4; pp++)
                ldsm_x4(b + pp * 4, lmbase + (uint32_t)(pp * 4096) + chx);

            #pragma unroll
            for (int p = 0; p < 8; p++) {
                mma16816(acc[0][p], fa0, fa1, fa2, fa3, b[p * 2], b[p * 2 + 1]);
                mma16816(acc[1][p], fb0, fb1, fb2, fb3, b[p * 2], b[p * 2 + 1]);
            }
            mma16816(zc[0], fa0, fa1, fa2, fa3, ONES, ONES);
            mma16816(zc[1], fb0, fb1, fb2, fb3, ONES, ONES);
        }
    }

    // epilogue: C frags -> g_part (stride 66, aligned float2)
    size_t rbase = (size_t)bx * 128 + row0;
    #pragma unroll
    for (int mt = 0; mt < 2; mt++) {
        #pragma unroll
        for (int p = 0; p < 8; p++) {
            float* o0 = g_part + (rbase + 16 * mt) * 66 + p * 8 + l4 * 2;
            float* o1 = o0 + 8 * 66;
            *(float2*)o0 = make_float2(acc[mt][p][0], acc[mt][p][1]);
            *(float2*)o1 = make_float2(acc[mt][p][2], acc[mt][p][3]);
        }
    }
    if (l4 == 0) {
        g_part[rbase * 66 + 64]        = zc[0][0];
        g_part[(rbase + 8) * 66 + 64]  = zc[0][2];
        g_part[(rbase + 16) * 66 + 64] = zc[1][0];
        g_part[(rbase + 24) * 66 + 64] = zc[1][2];
    }
}

// ---------------------------------------------------------------------------
// Kernel 4: combine 4 j-quarter partials, normalize, ELU (float2 vectorized)
// ---------------------------------------------------------------------------
__global__ __launch_bounds__(256) void combine_kernel(float* __restrict__ out) {
    int u = blockIdx.x * 256 + threadIdx.x;   // 0 .. 262143 (float2 units)
    int i = u >> 5, fp = u & 31;
    int b0 = (i >> 7) * 4, r = i & 127;
    const float* p = g_part + (size_t)(b0 * 128 + r) * 66;
    float nx = 0.f, ny = 0.f, z = 0.f;
    #pragma unroll
    for (int q = 0; q < 4; q++) {
        float2 v = *(const float2*)(p + (size_t)q * 128 * 66 + fp * 2);
        nx += v.x; ny += v.y;
        z += p[(size_t)q * 128 * 66 + 64];
    }
    float vx = nx / z, vy = ny / z;
    vx = (vx > 0.f) ? vx : expm1f(vx);
    vy = (vy > 0.f) ? vy : expm1f(vy);
    *(float2*)(out + (size_t)i * F_OUTD + fp * 2) = make_float2(vx, vy);
}

// ---------------------------------------------------------------------------
// Launch. Inputs: 0 h_nodes(8192x128 f32), 1 edge(8192 f32), 2 adj(8192^2 i32),
//                 3 weight(128x64 f32), 4 att(192 f32), 5 w_edge(64 f32)
// ---------------------------------------------------------------------------
extern "C" void kernel_launch(void* const* d_in, const int* in_sizes, int n_in,
                              void* d_out, int out_size) {
    const float* h      = (const float*)d_in[0];
    const float* edge   = (const float*)d_in[1];
    const int*   adj    = (const int*)d_in[2];
    const float* weight = (const float*)d_in[3];
    const float* att    = (const float*)d_in[4];
    const float* w_edge = (const float*)d_in[5];
    float* out = (float*)d_out;

    wh_kernel<<<NN / 32, 256>>>(h, weight);
    srcdst_kernel<<<NN / 8, 256>>>(edge, att, w_edge);
    packdst_kernel<<<NN / 512, 256>>>();
    attn_kernel<<<256, 128>>>(adj);
    combine_kernel<<<NN * F_OUTD / 512, 256>>>(out);
}

// round 12
// speedup vs baseline: 1.0546x; 1.0546x over previous
#include <cuda_runtime.h>
#include <cuda_fp16.h>
#include <cstdint>

#define NN     8192
#define F_IN   128
#define F_OUTD 64
#define L2E    1.4426950408889634f

#define ALPHA2_PK 0x32663266u   // half2(0.2, 0.2)
#define MESH2_PK  0xC5C5C5C5u   // half2(-5.7695, -5.7695) (~ -4*log2(e); uniform
                                // offset, cancels exactly in softmax)

// ---------------------------------------------------------------------------
// Device scratch (allocations forbidden -> __device__ globals)
// ---------------------------------------------------------------------------
__device__ float    g_wh[NN * F_OUTD];
__device__ __half   g_whT16[F_OUTD * NN];    // [f][i] fp16 transpose of wh
__device__ float    g_src[NN];
__device__ float    g_dst[NN];
__device__ uint32_t g_dst16u[NN / 2];        // half2(dst[2u], dst[2u+1]) * L2E
__device__ float    g_part[256 * 128 * 66];  // [cta][row][64 num, 1 Z, pad]

// ---------------------------------------------------------------------------
// Kernel 1: WH = H @ W (fp32) + fp16 transpose WH^T. 32 rows per block.
// ---------------------------------------------------------------------------
__global__ __launch_bounds__(256) void wh_kernel(const float* __restrict__ h,
                                                 const float* __restrict__ w) {
    __shared__ __align__(16) float sW[F_IN * F_OUTD];  // 32 KB
    __shared__ __align__(16) float sH[32 * F_IN];      // 16 KB (reused as sT)
    int t = threadIdx.x;
    int i0 = blockIdx.x * 32;

    {
        float4* dw = (float4*)sW;
        const float4* swg = (const float4*)w;
        #pragma unroll
        for (int k = 0; k < 8; k++) dw[t + k * 256] = swg[t + k * 256];
        float4* dh = (float4*)sH;
        const float4* shg = (const float4*)(h + (size_t)i0 * F_IN);
        #pragma unroll
        for (int k = 0; k < 4; k++) dh[t + k * 256] = shg[t + k * 256];
    }
    __syncthreads();

    int f = t & 63;
    int rg = t >> 6;
    float acc[8] = {0.f, 0.f, 0.f, 0.f, 0.f, 0.f, 0.f, 0.f};
    #pragma unroll 4
    for (int k = 0; k < F_IN; k += 4) {
        float w0 = sW[(k + 0) * F_OUTD + f];
        float w1 = sW[(k + 1) * F_OUTD + f];
        float w2 = sW[(k + 2) * F_OUTD + f];
        float w3 = sW[(k + 3) * F_OUTD + f];
        #pragma unroll
        for (int m = 0; m < 8; m++) {
            float4 h4 = *(const float4*)&sH[(rg * 8 + m) * F_IN + k];
            acc[m] = fmaf(h4.x, w0, acc[m]);
            acc[m] = fmaf(h4.y, w1, acc[m]);
            acc[m] = fmaf(h4.z, w2, acc[m]);
            acc[m] = fmaf(h4.w, w3, acc[m]);
        }
    }
    #pragma unroll
    for (int m = 0; m < 8; m++)
        g_wh[(size_t)(i0 + rg * 8 + m) * F_OUTD + f] = acc[m];

    __syncthreads();
    __half* sT = (__half*)sH;   // [64 f][32 r]
    #pragma unroll
    for (int m = 0; m < 8; m++)
        sT[f * 32 + rg * 8 + m] = __float2half_rn(acc[m]);
    __syncthreads();
    {
        int f2 = t >> 2, seg = t & 3;
        uint4 v = *(const uint4*)(sT + f2 * 32 + seg * 8);
        *(uint4*)(g_whT16 + (size_t)f2 * NN + i0 + seg * 8) = v;
    }
}

// ---------------------------------------------------------------------------
// Kernel 2: src / dst vectors
// ---------------------------------------------------------------------------
__global__ __launch_bounds__(256) void srcdst_kernel(const float* __restrict__ edge,
                                                     const float* __restrict__ att,
                                                     const float* __restrict__ w_edge) {
    int warp = threadIdx.x >> 5;
    int lane = threadIdx.x & 31;
    int i = blockIdx.x * 8 + warp;
    const float* whr = g_wh + (size_t)i * F_OUTD;

    float wl = whr[lane], wh2 = whr[lane + 32];
    float s = wl * att[lane]      + wh2 * att[lane + 32];
    float d = wl * att[64 + lane] + wh2 * att[96 + lane];
    float c = w_edge[lane] * att[128 + lane] + w_edge[lane + 32] * att[160 + lane];
    #pragma unroll
    for (int o = 16; o; o >>= 1) {
        s += __shfl_xor_sync(0xffffffffu, s, o);
        d += __shfl_xor_sync(0xffffffffu, d, o);
        c += __shfl_xor_sync(0xffffffffu, c, o);
    }
    if (lane == 0) {
        g_src[i] = s + edge[i] * c;
        g_dst[i] = d;
    }
}

// pack dst*L2E into half2 (even col in .lo)
__global__ __launch_bounds__(256) void packdst_kernel() {
    int u = blockIdx.x * 256 + threadIdx.x;   // 0..4095
    float2 d = *(const float2*)(g_dst + 2 * u);
    __half2 p = __floats2half2_rn(d.x * L2E, d.y * L2E);
    g_dst16u[u] = *(const uint32_t*)&p;
}

// ---------------------------------------------------------------------------
// mma.sync / ldmatrix / cp.async helpers
// ---------------------------------------------------------------------------
__device__ __forceinline__ uint32_t smem_u32(const void* p) {
    uint32_t a;
    asm("{ .reg .u64 t; cvta.to.shared.u64 t, %1; cvt.u32.u64 %0, t; }"
        : "=r"(a) : "l"(p));
    return a;
}
__device__ __forceinline__ void mma16816(float* c, uint32_t a0, uint32_t a1,
                                         uint32_t a2, uint32_t a3,
                                         uint32_t b0, uint32_t b1) {
    asm volatile(
        "mma.sync.aligned.m16n8k16.row.col.f32.f16.f16.f32 "
        "{%0,%1,%2,%3}, {%4,%5,%6,%7}, {%8,%9}, {%0,%1,%2,%3};"
        : "+f"(c[0]), "+f"(c[1]), "+f"(c[2]), "+f"(c[3])
        : "r"(a0), "r"(a1), "r"(a2), "r"(a3), "r"(b0), "r"(b1));
}
__device__ __forceinline__ void ldsm_x4(uint32_t* r, uint32_t addr) {
    asm volatile("ldmatrix.sync.aligned.m8n8.x4.shared.b16 {%0,%1,%2,%3}, [%4];"
                 : "=r"(r[0]), "=r"(r[1]), "=r"(r[2]), "=r"(r[3]) : "r"(addr));
}
__device__ __forceinline__ void cp_async16(uint32_t saddr, const void* gaddr) {
    asm volatile("cp.async.cg.shared.global [%0], [%1], 16;"
                 :: "r"(saddr), "l"(gaddr) : "memory");
}
__device__ __forceinline__ void cp_commit() {
    asm volatile("cp.async.commit_group;" ::: "memory");
}
__device__ __forceinline__ void cp_wait7() {
    asm volatile("cp.async.wait_group 7;" ::: "memory");
}
__device__ __forceinline__ int4 lds128(uint32_t addr) {
    int4 v;
    asm volatile("ld.shared.v4.u32 {%0,%1,%2,%3}, [%4];"
                 : "=r"(v.x), "=r"(v.y), "=r"(v.z), "=r"(v.w) : "r"(addr));
    return v;
}
// packed fp16 attention pair: src2/d2 already *L2E; mask by multiply.
// w = 2^( leaky(L2E*(src+dst)) - 4*L2E ) * mask
__device__ __forceinline__ uint32_t wpair16(uint32_t src2, uint32_t d2,
                                            int ax, int ay) {
    uint32_t e, m, l, g, w;
    asm("add.f16x2 %0, %1, %2;"    : "=r"(e) : "r"(src2), "r"(d2));
    asm("mul.f16x2 %0, %1, %2;"    : "=r"(m) : "r"(e), "r"(ALPHA2_PK));
    asm("max.f16x2 %0, %1, %2;"    : "=r"(l) : "r"(e), "r"(m));
    asm("add.f16x2 %0, %1, %2;"    : "=r"(g) : "r"(l), "r"(MESH2_PK));
    asm("ex2.approx.f16x2 %0, %0;" : "+r"(g));
    uint32_t msk = (uint32_t)ax * 0x3C00u + (uint32_t)ay * 0x3C000000u;
    asm("mul.f16x2 %0, %1, %2;"    : "=r"(w) : "r"(g), "r"(msk));
    return w;
}

// ---------------------------------------------------------------------------
// Kernel 3: HMMA masked-softmax aggregation. Round-10 shape (16 rows/warp,
// 256 thr, 2 CTAs/SM) + warp-private cp.async.cg adjacency ring in smem,
// depth 8 k-steps. cg bypasses L1 (L2->smem direct): kills the 16 adj L1
// wavefronts/warp-step and removes the register-ring scoreboard stalls that
// capped DRAM at 53%. Ring slot of step g is g&7 == ks (compile-time).
// Dynamic smem 96 KB: [0,64K) adj ring (8 warps x 8KB), [64K,96K) B dbl-buf.
// ---------------------------------------------------------------------------
__global__ void __launch_bounds__(256, 2) attn_kernel(const int* __restrict__ adj) {
    extern __shared__ __align__(1024) char sm[];
    char* sBreg = sm + 65536;                     // 2 x 16 KB B buffers

    int t = threadIdx.x, lane = t & 31, w = t >> 5;
    int bx = blockIdx.x;
    int i0 = (bx >> 2) * 128, j0 = (bx & 3) * 2048;

    int l4 = lane & 3;
    int lr = lane >> 2;
    int row0 = w * 16 + lr;

    float acc[8][4];
    float zc[4];
    #pragma unroll
    for (int p = 0; p < 8; p++)
        #pragma unroll
        for (int q = 0; q < 4; q++) acc[p][q] = 0.f;
    #pragma unroll
    for (int q = 0; q < 4; q++) zc[q] = 0.f;

    // src * L2E, replicated half2
    __half2 s0h = __float2half2_rn(g_src[i0 + row0] * L2E);
    __half2 s1h = __float2half2_rn(g_src[i0 + row0 + 8] * L2E);
    uint32_t srcL0 = *(const uint32_t*)&s0h;
    uint32_t srcL1 = *(const uint32_t*)&s1h;

    // adjacency: lane's global stream (one int4 per k-step per row-half)
    const int* gL = adj + (size_t)(i0 + row0) * NN + j0 + l4 * 4;
    const int* gH = gL + (size_t)8 * NN;
    // warp-private ring slab + per-lane offsets (lane-linear -> conflict-free)
    uint32_t sadj = smem_u32(sm) + (uint32_t)w * 8192u;
    uint32_t aoffL = (uint32_t)(lr * 64 + l4 * 16);
    uint32_t aoffH = aoffL + 512u;
    // dst base: half2 units
    const uint32_t* dpp = g_dst16u + (j0 >> 1) + l4 * 2;

    // B-copy indices
    int fB = t >> 2, qb = (t & 3) * 4;
    const uint4* bsrc_base = (const uint4*)(g_whT16 + (size_t)fB * NN + j0);
    // ldmatrix per-lane geometry
    int fo  = (lane & 7) + ((lane & 16) >> 1);
    int cb  = (lane >> 3) & 1;
    int sw7 = lane & 7;
    uint32_t sb_base = smem_u32(sm) + 65536u;

    // B staging with half2-unit deinterleave per 32B group
    #define STAGE_B(dstbuf, srcptr)                                             \
        do {                                                                    \
            uint4 v0 = (srcptr)[qb], v1 = (srcptr)[qb + 1];                     \
            uint4 v2 = (srcptr)[qb + 2], v3 = (srcptr)[qb + 3];                 \
            uint4 o0 = make_uint4(v0.x, v0.z, v1.x, v1.z);                      \
            uint4 o1 = make_uint4(v0.y, v0.w, v1.y, v1.w);                      \
            uint4 o2 = make_uint4(v2.x, v2.z, v3.x, v3.z);                      \
            uint4 o3 = make_uint4(v2.y, v2.w, v3.y, v3.w);                      \
            char* db = (char*)(dstbuf) + (size_t)fB * 256;                      \
            *(uint4*)(db + (((qb + 0) ^ (fB & 7)) << 4)) = o0;                  \
            *(uint4*)(db + (((qb + 1) ^ (fB & 7)) << 4)) = o1;                  \
            *(uint4*)(db + (((qb + 2) ^ (fB & 7)) << 4)) = o2;                  \
            *(uint4*)(db + (((qb + 3) ^ (fB & 7)) << 4)) = o3;                  \
        } while (0)

    // prologue: adj ring slots 0..7 (= steps 0..7), one commit group per step
    #pragma unroll
    for (int st = 0; st < 8; st++) {
        cp_async16(sadj + (uint32_t)st * 1024u + aoffL, gL + st * 16);
        cp_async16(sadj + (uint32_t)st * 1024u + aoffH, gH + st * 16);
        cp_commit();
    }
    // dst ring prologue (L2-resident, register ring depth 2)
    uint2 rD[2];
    rD[0] = *(const uint2*)(dpp);
    rD[1] = *(const uint2*)(dpp + 8);
    // B buffer 0
    STAGE_B(sBreg, bsrc_base);

    // first consumer registers: slot 0 (group 0 done after wait<=7)
    cp_wait7();
    int4 c0L = lds128(sadj + aoffL);
    int4 c0H = lds128(sadj + aoffH);
    int4 c1L, c1H;

    const uint32_t ONES = 0x3C003C00u;  // fp16 {1,1}

    for (int lt = 0; lt < 16; lt++) {
        int s = lt & 1;
        __syncthreads();
        if (lt < 15) {   // prefetch next B tile into the other buffer
            const uint4* bs = (const uint4*)((const __half*)bsrc_base + (lt + 1) * 128);
            STAGE_B(sBreg + (s ^ 1) * 16384, bs);
        }

        uint32_t lmbase = sb_base + (uint32_t)s * 16384u + (uint32_t)fo * 256u;
        int gbase = lt * 8;
        const int* gLt = gL + (gbase + 8) * 16;   // refill sources this tile
        const int* gHt = gH + (gbase + 8) * 16;
        bool refill = (lt < 15);

        #pragma unroll
        for (int ks = 0; ks < 8; ks++) {          // ks literal (unrolled)
            // consume current registers (slot ks), alternating sets
            int4 aL = (ks & 1) ? c1L : c0L;
            int4 aH = (ks & 1) ? c1H : c0H;
            uint2 dd = rD[ks & 1];

            // refill ring slot ks with step g+8 (predicated; commit ALWAYS
            // so group numbering stays uniform — empty groups complete now)
            if (refill) {
                cp_async16(sadj + (uint32_t)ks * 1024u + aoffL, gLt + ks * 16);
                cp_async16(sadj + (uint32_t)ks * 1024u + aoffH, gHt + ks * 16);
            }
            cp_commit();
            // dst refill for step g+2
            if (lt < 15 || ks < 6)
                rD[ks & 1] = *(const uint2*)(dpp + (gbase + ks + 2) * 8);

            // ensure group for step g+1 is done, stage its registers
            cp_wait7();
            {
                uint32_t na = sadj + (uint32_t)((ks + 1) & 7) * 1024u;
                if (ks & 1) { c0L = lds128(na + aoffL); c0H = lds128(na + aoffH); }
                else        { c1L = lds128(na + aoffL); c1H = lds128(na + aoffH); }
            }

            // A fragments
            uint32_t fa0 = wpair16(srcL0, dd.x, aL.x, aL.y);   // rows 0-7,  k-lo
            uint32_t fa1 = wpair16(srcL1, dd.x, aH.x, aH.y);   // rows 8-15, k-lo
            uint32_t fa2 = wpair16(srcL0, dd.y, aL.z, aL.w);   // rows 0-7,  k-hi
            uint32_t fa3 = wpair16(srcL1, dd.y, aH.z, aH.w);   // rows 8-15, k-hi

            uint32_t chx = (uint32_t)(((2 * ks + cb) ^ sw7) << 4);
            uint32_t b[16];
            #pragma unroll
            for (int pp = 0; pp < 4; pp++)
                ldsm_x4(b + pp * 4, lmbase + (uint32_t)(pp * 4096) + chx);

            #pragma unroll
            for (int p = 0; p < 8; p++)
                mma16816(acc[p], fa0, fa1, fa2, fa3, b[p * 2], b[p * 2 + 1]);
            mma16816(zc, fa0, fa1, fa2, fa3, ONES, ONES);
        }
    }

    // epilogue: C frags -> g_part (stride 66, aligned float2)
    size_t rbase = (size_t)bx * 128 + row0;
    #pragma unroll
    for (int p = 0; p < 8; p++) {
        float* o0 = g_part + rbase * 66 + p * 8 + l4 * 2;
        float* o1 = o0 + 8 * 66;
        *(float2*)o0 = make_float2(acc[p][0], acc[p][1]);
        *(float2*)o1 = make_float2(acc[p][2], acc[p][3]);
    }
    if (l4 == 0) {
        g_part[rbase * 66 + 64] = zc[0];
        g_part[(rbase + 8) * 66 + 64] = zc[2];
    }
}

// ---------------------------------------------------------------------------
// Kernel 4: combine 4 j-quarter partials, normalize, ELU (float2 vectorized)
// ---------------------------------------------------------------------------
__global__ __launch_bounds__(256) void combine_kernel(float* __restrict__ out) {
    int u = blockIdx.x * 256 + threadIdx.x;   // 0 .. 262143 (float2 units)
    int i = u >> 5, fp = u & 31;
    int b0 = (i >> 7) * 4, r = i & 127;
    const float* p = g_part + (size_t)(b0 * 128 + r) * 66;
    float nx = 0.f, ny = 0.f, z = 0.f;
    #pragma unroll
    for (int q = 0; q < 4; q++) {
        float2 v = *(const float2*)(p + (size_t)q * 128 * 66 + fp * 2);
        nx += v.x; ny += v.y;
        z += p[(size_t)q * 128 * 66 + 64];
    }
    float vx = nx / z, vy = ny / z;
    vx = (vx > 0.f) ? vx : expm1f(vx);
    vy = (vy > 0.f) ? vy : expm1f(vy);
    *(float2*)(out + (size_t)i * F_OUTD + fp * 2) = make_float2(vx, vy);
}

// ---------------------------------------------------------------------------
// Launch. Inputs: 0 h_nodes(8192x128 f32), 1 edge(8192 f32), 2 adj(8192^2 i32),
//                 3 weight(128x64 f32), 4 att(192 f32), 5 w_edge(64 f32)
// ---------------------------------------------------------------------------
extern "C" void kernel_launch(void* const* d_in, const int* in_sizes, int n_in,
                              void* d_out, int out_size) {
    const float* h      = (const float*)d_in[0];
    const float* edge   = (const float*)d_in[1];
    const int*   adj    = (const int*)d_in[2];
    const float* weight = (const float*)d_in[3];
    const float* att    = (const float*)d_in[4];
    const float* w_edge = (const float*)d_in[5];
    float* out = (float*)d_out;

    cudaFuncSetAttribute(attn_kernel,
                         cudaFuncAttributeMaxDynamicSharedMemorySize, 98304);

    wh_kernel<<<NN / 32, 256>>>(h, weight);
    srcdst_kernel<<<NN / 8, 256>>>(edge, att, w_edge);
    packdst_kernel<<<NN / 512, 256>>>();
    attn_kernel<<<256, 256, 98304>>>(adj);
    combine_kernel<<<NN * F_OUTD / 512, 256>>>(out);
}

// round 13
// speedup vs baseline: 1.1046x; 1.0474x over previous
#include <cuda_runtime.h>
#include <cuda_fp16.h>
#include <cstdint>

#define NN     8192
#define F_IN   128
#define F_OUTD 64
#define L2E    1.4426950408889634f

#define ALPHA2_PK 0x32663266u   // half2(0.2, 0.2)
#define MESH2_PK  0xC5C5C5C5u   // half2(-5.7695, -5.7695) (~ -4*log2(e); uniform
                                // offset, cancels exactly in softmax)

// ---------------------------------------------------------------------------
// Device scratch (allocations forbidden -> __device__ globals)
// ---------------------------------------------------------------------------
__device__ float    g_wh[NN * F_OUTD];
__device__ __half   g_whT16[F_OUTD * NN];    // [f][i] fp16 transpose of wh
__device__ float    g_src[NN];
__device__ __half   g_dst16h[NN];            // dst[i] * L2E as fp16
__device__ float    g_part[256 * 128 * 68];  // [cta][row][64 num, Z, pad..]

// ---------------------------------------------------------------------------
// Kernel 1: WH = H @ W (fp32) + fp16 transpose WH^T. 32 rows per block.
// ---------------------------------------------------------------------------
__global__ __launch_bounds__(256) void wh_kernel(const float* __restrict__ h,
                                                 const float* __restrict__ w) {
    __shared__ __align__(16) float sW[F_IN * F_OUTD];  // 32 KB
    __shared__ __align__(16) float sH[32 * F_IN];      // 16 KB (reused as sT)
    int t = threadIdx.x;
    int i0 = blockIdx.x * 32;

    {
        float4* dw = (float4*)sW;
        const float4* swg = (const float4*)w;
        #pragma unroll
        for (int k = 0; k < 8; k++) dw[t + k * 256] = swg[t + k * 256];
        float4* dh = (float4*)sH;
        const float4* shg = (const float4*)(h + (size_t)i0 * F_IN);
        #pragma unroll
        for (int k = 0; k < 4; k++) dh[t + k * 256] = shg[t + k * 256];
    }
    __syncthreads();

    int f = t & 63;
    int rg = t >> 6;
    float acc[8] = {0.f, 0.f, 0.f, 0.f, 0.f, 0.f, 0.f, 0.f};
    #pragma unroll 4
    for (int k = 0; k < F_IN; k += 4) {
        float w0 = sW[(k + 0) * F_OUTD + f];
        float w1 = sW[(k + 1) * F_OUTD + f];
        float w2 = sW[(k + 2) * F_OUTD + f];
        float w3 = sW[(k + 3) * F_OUTD + f];
        #pragma unroll
        for (int m = 0; m < 8; m++) {
            float4 h4 = *(const float4*)&sH[(rg * 8 + m) * F_IN + k];
            acc[m] = fmaf(h4.x, w0, acc[m]);
            acc[m] = fmaf(h4.y, w1, acc[m]);
            acc[m] = fmaf(h4.z, w2, acc[m]);
            acc[m] = fmaf(h4.w, w3, acc[m]);
        }
    }
    #pragma unroll
    for (int m = 0; m < 8; m++)
        g_wh[(size_t)(i0 + rg * 8 + m) * F_OUTD + f] = acc[m];

    __syncthreads();
    __half* sT = (__half*)sH;   // [64 f][32 r]
    #pragma unroll
    for (int m = 0; m < 8; m++)
        sT[f * 32 + rg * 8 + m] = __float2half_rn(acc[m]);
    __syncthreads();
    {
        int f2 = t >> 2, seg = t & 3;
        uint4 v = *(const uint4*)(sT + f2 * 32 + seg * 8);
        *(uint4*)(g_whT16 + (size_t)f2 * NN + i0 + seg * 8) = v;
    }
}

// ---------------------------------------------------------------------------
// Kernel 2: src / dst vectors (dst written directly as fp16 * L2E)
// ---------------------------------------------------------------------------
__global__ __launch_bounds__(256) void srcdst_kernel(const float* __restrict__ edge,
                                                     const float* __restrict__ att,
                                                     const float* __restrict__ w_edge) {
    int warp = threadIdx.x >> 5;
    int lane = threadIdx.x & 31;
    int i = blockIdx.x * 8 + warp;
    const float* whr = g_wh + (size_t)i * F_OUTD;

    float wl = whr[lane], wh2 = whr[lane + 32];
    float s = wl * att[lane]      + wh2 * att[lane + 32];
    float d = wl * att[64 + lane] + wh2 * att[96 + lane];
    float c = w_edge[lane] * att[128 + lane] + w_edge[lane + 32] * att[160 + lane];
    #pragma unroll
    for (int o = 16; o; o >>= 1) {
        s += __shfl_xor_sync(0xffffffffu, s, o);
        d += __shfl_xor_sync(0xffffffffu, d, o);
        c += __shfl_xor_sync(0xffffffffu, c, o);
    }
    if (lane == 0) {
        g_src[i] = s + edge[i] * c;
        g_dst16h[i] = __float2half_rn(d * L2E);
    }
}

// ---------------------------------------------------------------------------
// mma.sync / ldmatrix / cp.async helpers
// ---------------------------------------------------------------------------
__device__ __forceinline__ uint32_t smem_u32(const void* p) {
    uint32_t a;
    asm("{ .reg .u64 t; cvta.to.shared.u64 t, %1; cvt.u32.u64 %0, t; }"
        : "=r"(a) : "l"(p));
    return a;
}
__device__ __forceinline__ void mma16816(float* c, uint32_t a0, uint32_t a1,
                                         uint32_t a2, uint32_t a3,
                                         uint32_t b0, uint32_t b1) {
    asm volatile(
        "mma.sync.aligned.m16n8k16.row.col.f32.f16.f16.f32 "
        "{%0,%1,%2,%3}, {%4,%5,%6,%7}, {%8,%9}, {%0,%1,%2,%3};"
        : "+f"(c[0]), "+f"(c[1]), "+f"(c[2]), "+f"(c[3])
        : "r"(a0), "r"(a1), "r"(a2), "r"(a3), "r"(b0), "r"(b1));
}
__device__ __forceinline__ void ldsm_x4(uint32_t* r, uint32_t addr) {
    asm volatile("ldmatrix.sync.aligned.m8n8.x4.shared.b16 {%0,%1,%2,%3}, [%4];"
                 : "=r"(r[0]), "=r"(r[1]), "=r"(r[2]), "=r"(r[3]) : "r"(addr));
}
__device__ __forceinline__ void cp_async16(uint32_t saddr, const void* gaddr) {
    asm volatile("cp.async.cg.shared.global [%0], [%1], 16;"
                 :: "r"(saddr), "l"(gaddr) : "memory");
}
__device__ __forceinline__ void cp_commit() {
    asm volatile("cp.async.commit_group;" ::: "memory");
}
__device__ __forceinline__ void cp_wait7() {
    asm volatile("cp.async.wait_group 7;" ::: "memory");
}
__device__ __forceinline__ int4 lds128(uint32_t addr) {
    int4 v;
    asm volatile("ld.shared.v4.u32 {%0,%1,%2,%3}, [%4];"
                 : "=r"(v.x), "=r"(v.y), "=r"(v.z), "=r"(v.w) : "r"(addr));
    return v;
}
// packed fp16 attention pair: src2/d2 already *L2E; mask by multiply.
// w = 2^( leaky(L2E*(src+dst)) - 4*L2E ) * mask
__device__ __forceinline__ uint32_t wpair16(uint32_t src2, uint32_t d2,
                                            int ax, int ay) {
    uint32_t e, m, l, g, w;
    asm("add.f16x2 %0, %1, %2;"    : "=r"(e) : "r"(src2), "r"(d2));
    asm("mul.f16x2 %0, %1, %2;"    : "=r"(m) : "r"(e), "r"(ALPHA2_PK));
    asm("max.f16x2 %0, %1, %2;"    : "=r"(l) : "r"(e), "r"(m));
    asm("add.f16x2 %0, %1, %2;"    : "=r"(g) : "r"(l), "r"(MESH2_PK));
    asm("ex2.approx.f16x2 %0, %0;" : "+r"(g));
    uint32_t msk = (uint32_t)ax * 0x3C00u + (uint32_t)ay * 0x3C000000u;
    asm("mul.f16x2 %0, %1, %2;"    : "=r"(w) : "r"(g), "r"(msk));
    return w;
}

// ---------------------------------------------------------------------------
// Kernel 3: HMMA masked-softmax aggregation. Round-12 core (cp.async.cg adj
// ring, depth 8, slot = ks literal) with the B tile staging split: LDGs issue
// at tile top, deinterleave+STS lands after step 2 (~350 cyc later), hiding
// the B load latency behind MMA work instead of stalling at the tile top.
// Dynamic smem 96 KB: [0,64K) adj ring (8 warps x 8KB), [64K,96K) B dbl-buf.
// ---------------------------------------------------------------------------
__global__ void __launch_bounds__(256, 2) attn_kernel(const int* __restrict__ adj) {
    extern __shared__ __align__(1024) char sm[];
    char* sBreg = sm + 65536;                     // 2 x 16 KB B buffers

    int t = threadIdx.x, lane = t & 31, w = t >> 5;
    int bx = blockIdx.x;
    int i0 = (bx >> 2) * 128, j0 = (bx & 3) * 2048;

    int l4 = lane & 3;
    int lr = lane >> 2;
    int row0 = w * 16 + lr;

    float acc[8][4];
    float zc[4];
    #pragma unroll
    for (int p = 0; p < 8; p++)
        #pragma unroll
        for (int q = 0; q < 4; q++) acc[p][q] = 0.f;
    #pragma unroll
    for (int q = 0; q < 4; q++) zc[q] = 0.f;

    // src * L2E, replicated half2
    __half2 s0h = __float2half2_rn(g_src[i0 + row0] * L2E);
    __half2 s1h = __float2half2_rn(g_src[i0 + row0 + 8] * L2E);
    uint32_t srcL0 = *(const uint32_t*)&s0h;
    uint32_t srcL1 = *(const uint32_t*)&s1h;

    // adjacency: lane's global stream (one int4 per k-step per row-half)
    const int* gL = adj + (size_t)(i0 + row0) * NN + j0 + l4 * 4;
    const int* gH = gL + (size_t)8 * NN;
    // warp-private ring slab + per-lane offsets (lane-linear -> conflict-free)
    uint32_t sadj = smem_u32(sm) + (uint32_t)w * 8192u;
    uint32_t aoffL = (uint32_t)(lr * 64 + l4 * 16);
    uint32_t aoffH = aoffL + 512u;
    // dst base: half2 units
    const uint32_t* dpp = (const uint32_t*)g_dst16h + (j0 >> 1) + l4 * 2;

    // B-copy indices
    int fB = t >> 2, qb = (t & 3) * 4;
    const uint4* bsrc_base = (const uint4*)(g_whT16 + (size_t)fB * NN + j0);
    // ldmatrix per-lane geometry
    int fo  = (lane & 7) + ((lane & 16) >> 1);
    int cb  = (lane >> 3) & 1;
    int sw7 = lane & 7;
    uint32_t sb_base = smem_u32(sm) + 65536u;

    // prologue: adj ring slots 0..7 (= steps 0..7), one commit group per step
    #pragma unroll
    for (int st = 0; st < 8; st++) {
        cp_async16(sadj + (uint32_t)st * 1024u + aoffL, gL + st * 16);
        cp_async16(sadj + (uint32_t)st * 1024u + aoffH, gH + st * 16);
        cp_commit();
    }
    // dst ring prologue (L2-resident, register ring depth 2)
    uint2 rD[2];
    rD[0] = *(const uint2*)(dpp);
    rD[1] = *(const uint2*)(dpp + 8);
    // B buffer 0 (direct stage: load + deinterleave + store)
    {
        uint4 v0 = bsrc_base[qb], v1 = bsrc_base[qb + 1];
        uint4 v2 = bsrc_base[qb + 2], v3 = bsrc_base[qb + 3];
        char* db = sBreg + (size_t)fB * 256;
        uint4 o0 = make_uint4(v0.x, v0.z, v1.x, v1.z);
        uint4 o1 = make_uint4(v0.y, v0.w, v1.y, v1.w);
        uint4 o2 = make_uint4(v2.x, v2.z, v3.x, v3.z);
        uint4 o3 = make_uint4(v2.y, v2.w, v3.y, v3.w);
        *(uint4*)(db + (((qb + 0) ^ (fB & 7)) << 4)) = o0;
        *(uint4*)(db + (((qb + 1) ^ (fB & 7)) << 4)) = o1;
        *(uint4*)(db + (((qb + 2) ^ (fB & 7)) << 4)) = o2;
        *(uint4*)(db + (((qb + 3) ^ (fB & 7)) << 4)) = o3;
    }

    // first consumer registers: slot 0 (group 0 done after wait<=7)
    cp_wait7();
    int4 c0L = lds128(sadj + aoffL);
    int4 c0H = lds128(sadj + aoffH);
    int4 c1L, c1H;

    const uint32_t ONES = 0x3C003C00u;  // fp16 {1,1}

    // one k-step; ks must be a compile-time literal
    #define STEP(ks)                                                            \
        do {                                                                    \
            int4 aL = ((ks) & 1) ? c1L : c0L;                                   \
            int4 aH = ((ks) & 1) ? c1H : c0H;                                   \
            uint2 dd = rD[(ks) & 1];                                            \
            if (refill) {                                                       \
                cp_async16(sadj + (uint32_t)(ks) * 1024u + aoffL,               \
                           gLt + (ks) * 16);                                    \
                cp_async16(sadj + (uint32_t)(ks) * 1024u + aoffH,               \
                           gHt + (ks) * 16);                                    \
            }                                                                   \
            cp_commit();                                                        \
            if (refill || (ks) < 6)                                             \
                rD[(ks) & 1] = *(const uint2*)(dpp + (gbase + (ks) + 2) * 8);   \
            cp_wait7();                                                         \
            {                                                                   \
                uint32_t na = sadj + (uint32_t)(((ks) + 1) & 7) * 1024u;        \
                if ((ks) & 1) { c0L = lds128(na + aoffL);                       \
                                c0H = lds128(na + aoffH); }                     \
                else          { c1L = lds128(na + aoffL);                       \
                                c1H = lds128(na + aoffH); }                     \
            }                                                                   \
            uint32_t fa0 = wpair16(srcL0, dd.x, aL.x, aL.y);                    \
            uint32_t fa1 = wpair16(srcL1, dd.x, aH.x, aH.y);                    \
            uint32_t fa2 = wpair16(srcL0, dd.y, aL.z, aL.w);                    \
            uint32_t fa3 = wpair16(srcL1, dd.y, aH.z, aH.w);                    \
            uint32_t chx = (uint32_t)(((2 * (ks) + cb) ^ sw7) << 4);            \
            uint32_t b[16];                                                     \
            _Pragma("unroll")                                                   \
            for (int pp = 0; pp < 4; pp++)                                      \
                ldsm_x4(b + pp * 4, lmbase + (uint32_t)(pp * 4096) + chx);      \
            _Pragma("unroll")                                                   \
            for (int p = 0; p < 8; p++)                                         \
                mma16816(acc[p], fa0, fa1, fa2, fa3, b[p * 2], b[p * 2 + 1]);   \
            mma16816(zc, fa0, fa1, fa2, fa3, ONES, ONES);                       \
        } while (0)

    for (int lt = 0; lt < 16; lt++) {
        int s = lt & 1;
        __syncthreads();

        // issue next-tile B loads NOW; store after step 2
        uint4 v0, v1, v2, v3;
        bool refill = (lt < 15);
        if (refill) {
            const uint4* bs = bsrc_base + (lt + 1) * 16;
            v0 = bs[qb]; v1 = bs[qb + 1]; v2 = bs[qb + 2]; v3 = bs[qb + 3];
        }

        uint32_t lmbase = sb_base + (uint32_t)s * 16384u + (uint32_t)fo * 256u;
        int gbase = lt * 8;
        const int* gLt = gL + (gbase + 8) * 16;
        const int* gHt = gH + (gbase + 8) * 16;

        STEP(0); STEP(1); STEP(2);

        if (refill) {   // B deinterleave + store, ~350 cyc after the loads
            char* db = sBreg + (s ^ 1) * 16384 + (size_t)fB * 256;
            uint4 o0 = make_uint4(v0.x, v0.z, v1.x, v1.z);
            uint4 o1 = make_uint4(v0.y, v0.w, v1.y, v1.w);
            uint4 o2 = make_uint4(v2.x, v2.z, v3.x, v3.z);
            uint4 o3 = make_uint4(v2.y, v2.w, v3.y, v3.w);
            *(uint4*)(db + (((qb + 0) ^ (fB & 7)) << 4)) = o0;
            *(uint4*)(db + (((qb + 1) ^ (fB & 7)) << 4)) = o1;
            *(uint4*)(db + (((qb + 2) ^ (fB & 7)) << 4)) = o2;
            *(uint4*)(db + (((qb + 3) ^ (fB & 7)) << 4)) = o3;
        }

        STEP(3); STEP(4); STEP(5); STEP(6); STEP(7);
    }
    #undef STEP

    // epilogue: C frags -> g_part (stride 68, float2-aligned)
    size_t rbase = (size_t)bx * 128 + row0;
    #pragma unroll
    for (int p = 0; p < 8; p++) {
        float* o0 = g_part + rbase * 68 + p * 8 + l4 * 2;
        float* o1 = o0 + 8 * 68;
        *(float2*)o0 = make_float2(acc[p][0], acc[p][1]);
        *(float2*)o1 = make_float2(acc[p][2], acc[p][3]);
    }
    if (l4 == 0) {
        g_part[rbase * 68 + 64] = zc[0];
        g_part[(rbase + 8) * 68 + 64] = zc[2];
    }
}

// ---------------------------------------------------------------------------
// Kernel 4: combine 4 j-quarter partials, normalize, ELU. float4 + 4-quarter
// ILP (8 outstanding loads per thread).
// ---------------------------------------------------------------------------
__global__ __launch_bounds__(256) void combine_kernel(float* __restrict__ out) {
    int u = blockIdx.x * 256 + threadIdx.x;   // 0 .. 131071 (float4 units)
    int i = u >> 4, fq = u & 15;
    int b0 = (i >> 7) * 4, r = i & 127;
    const float* p = g_part + (size_t)(b0 * 128 + r) * 68 + fq * 4;
    const float* pz = g_part + (size_t)(b0 * 128 + r) * 68 + 64;
    float nx = 0.f, ny = 0.f, nz = 0.f, nw = 0.f, z = 0.f;
    #pragma unroll
    for (int q = 0; q < 4; q++) {
        float4 v = *(const float4*)(p + (size_t)q * 128 * 68);
        nx += v.x; ny += v.y; nz += v.z; nw += v.w;
        z += pz[(size_t)q * 128 * 68];
    }
    float4 o;
    o.x = nx / z; o.y = ny / z; o.z = nz / z; o.w = nw / z;
    o.x = (o.x > 0.f) ? o.x : expm1f(o.x);
    o.y = (o.y > 0.f) ? o.y : expm1f(o.y);
    o.z = (o.z > 0.f) ? o.z : expm1f(o.z);
    o.w = (o.w > 0.f) ? o.w : expm1f(o.w);
    *(float4*)(out + (size_t)i * F_OUTD + fq * 4) = o;
}

// ---------------------------------------------------------------------------
// Launch. Inputs: 0 h_nodes(8192x128 f32), 1 edge(8192 f32), 2 adj(8192^2 i32),
//                 3 weight(128x64 f32), 4 att(192 f32), 5 w_edge(64 f32)
// ---------------------------------------------------------------------------
extern "C" void kernel_launch(void* const* d_in, const int* in_sizes, int n_in,
                              void* d_out, int out_size) {
    const float* h      = (const float*)d_in[0];
    const float* edge   = (const float*)d_in[1];
    const int*   adj    = (const int*)d_in[2];
    const float* weight = (const float*)d_in[3];
    const float* att    = (const float*)d_in[4];
    const float* w_edge = (const float*)d_in[5];
    float* out = (float*)d_out;

    cudaFuncSetAttribute(attn_kernel,
                         cudaFuncAttributeMaxDynamicSharedMemorySize, 98304);

    wh_kernel<<<NN / 32, 256>>>(h, weight);
    srcdst_kernel<<<NN / 8, 256>>>(edge, att, w_edge);
    attn_kernel<<<256, 256, 98304>>>(adj);
    combine_kernel<<<NN * F_OUTD / 1024, 256>>>(out);
}